// round 14
// baseline (speedup 1.0000x reference)
#include <cuda_runtime.h>
#include <cuda_fp16.h>
#include <math.h>
#include <stdint.h>

#define MAXN 50000
#define PADN (MAXN + 128)
#define MAXE 800000
#define MAXG 64

// ---------------- scratch ---------------------------------------------------------
__device__ float    g_h[(size_t)MAXN * 256];     // GEMM output (fp32, pre-aggregation)
__device__ float    g_agg[(size_t)MAXN * 64];    // layer-3 aggregation output (fp32)
__device__ __half   g_ah[(size_t)PADN * 512];    // GEMM A input, fp16 hi
__device__ __half   g_al[(size_t)PADN * 512];    // GEMM A input, fp16 lo
__device__ uint32_t g_wh[86016];                 // weights, k-pair fp16x2 hi (3 layers)
__device__ uint32_t g_wl[86016];                 // weights, k-pair fp16x2 lo
__device__ float    g_dinv[MAXN];
__device__ int      g_deg[MAXN];
__device__ int      g_rowptr[MAXN + 1];
__device__ int      g_fill[MAXN];
__device__ int      g_col[MAXE];
__device__ float    g_pool[MAXG * 64];
__device__ int      g_cnt[MAXG];
__device__ int      g_is64;

// ---------------- helpers ---------------------------------------------------------
__device__ __forceinline__ uint32_t smem_to_u32_helper(const void* smem_ptr) {
    uint32_t addr;
    asm("{ .reg .u64 tmp; cvta.to.shared.u64 tmp, %1; cvt.u32.u64 %0, tmp; }"
        : "=r"(addr) : "l"(smem_ptr));
    return addr;
}

// ---------------- index dtype detection (int64 vs int32) -------------------------
__global__ void detect_k(const void* ei) {
    __shared__ int nz;
    if (threadIdx.x == 0) nz = 0;
    __syncthreads();
    const int* p = (const int*)ei;
    if (p[2 * threadIdx.x + 1] != 0) atomicAdd(&nz, 1);
    __syncthreads();
    if (threadIdx.x == 0) g_is64 = (nz == 0) ? 1 : 0;
}

__device__ __forceinline__ int load_idx(const void* p, long long i, int is64) {
    if (is64) return (int)((const long long*)p)[i];
    return ((const int*)p)[i];
}

// ---------------- init ------------------------------------------------------------
__global__ void init_k(int n) {
    int i = blockIdx.x * blockDim.x + threadIdx.x;
    int stride = gridDim.x * blockDim.x;
    for (; i < n; i += stride) {
        g_deg[i]  = 1;
        g_fill[i] = 0;
        if (i < MAXG * 64) g_pool[i] = 0.0f;
        if (i < MAXG) g_cnt[i] = 0;
    }
}

__global__ void deg_k(const void* ei, int E) {
    int e = blockIdx.x * blockDim.x + threadIdx.x;
    if (e >= E) return;
    int is64 = g_is64;
    int d = load_idx(ei, (long long)E + e, is64);
    atomicAdd(&g_deg[d], 1);
}

__global__ void dinv_k(int n) {
    int i = blockIdx.x * blockDim.x + threadIdx.x;
    if (i < n) g_dinv[i] = rsqrtf((float)g_deg[i]);
}

// ---------------- single-block exclusive scan of (deg-1) -> rowptr ----------------
__global__ void scan_k(int n) {
    __shared__ int part[1024];
    int t = threadIdx.x;
    int C = (n + 1023) / 1024;
    int lo = t * C;
    int hi = min(lo + C, n);
    int s = 0;
    for (int i = lo; i < hi; i++) s += g_deg[i] - 1;
    part[t] = s;
    __syncthreads();
    for (int off = 1; off < 1024; off <<= 1) {
        int v = (t >= off) ? part[t - off] : 0;
        __syncthreads();
        part[t] += v;
        __syncthreads();
    }
    int run = (t == 0) ? 0 : part[t - 1];
    for (int i = lo; i < hi; i++) {
        g_rowptr[i] = run;
        run += g_deg[i] - 1;
    }
    if (t == 1023) g_rowptr[n] = part[1023];
}

__global__ void scat_k(const void* ei, int E) {
    int e = blockIdx.x * blockDim.x + threadIdx.x;
    if (e >= E) return;
    int is64 = g_is64;
    int s = load_idx(ei, e, is64);
    int d = load_idx(ei, (long long)E + e, is64);
    int pos = atomicAdd(&g_fill[d], 1);
    g_col[g_rowptr[d] + pos] = s;
}

// ---------------- fp16 hi/lo split helpers ----------------------------------------
__device__ __forceinline__ __half2 split_hi2(float x, float y) {
    __half2 h; h.x = __float2half_rn(x); h.y = __float2half_rn(y); return h;
}
__device__ __forceinline__ __half2 split_lo2(float x, float y, __half2 h) {
    __half2 l;
    l.x = __float2half_rn(x - __half2float(h.x));
    l.y = __float2half_rn(y - __half2float(h.y));
    return l;
}

// ---------------- x -> fp16 hi/lo conversion --------------------------------------
__global__ void convx_k(const float* __restrict__ x, int total2) {
    int i = blockIdx.x * blockDim.x + threadIdx.x;
    if (i >= total2) return;
    float2 v = ((const float2*)x)[i];
    __half2 h = split_hi2(v.x, v.y);
    __half2 l = split_lo2(v.x, v.y, h);
    ((__half2*)g_ah)[i] = h;
    ((__half2*)g_al)[i] = l;
}

// ---------------- W -> k-pair-packed fp16x2 hi/lo ---------------------------------
__global__ void convw_k(const float* __restrict__ W, int K, int Nc, int off) {
    int id = blockIdx.x * blockDim.x + threadIdx.x;
    int tot = (K / 2) * Nc;
    if (id >= tot) return;
    int k2 = id / Nc, nn = id - k2 * Nc;
    float w0 = W[(size_t)(2 * k2) * Nc + nn];
    float w1 = W[(size_t)(2 * k2 + 1) * Nc + nn];
    __half2 h = split_hi2(w0, w1);
    __half2 l = split_lo2(w0, w1, h);
    g_wh[off + id] = *(uint32_t*)&h;
    g_wl[off + id] = *(uint32_t*)&l;
}

// =================== 3-term fp16 HMMA GEMM (cp.async pipelined) ===================
// C[M x Nc] fp32 = (Ah+Al) @ (Bh+Bl), dropping Al*Bl.
// Block 128x64, 4 warps (warp tile 64x32), BK=32, double-buffered cp.async.
// Smem layout per buffer (bytes): AH[128][20 u32]=10240, AL=10240,
//                                 BH[16][72 u32]=4608, BL=4608 -> 29696/buffer.
#define HG_BUF   29696
#define HG_SMEM  (2 * HG_BUF)

__device__ __forceinline__ void mma_f16(float* d, const uint32_t* a, const uint32_t* b) {
    asm volatile(
        "mma.sync.aligned.m16n8k16.row.col.f32.f16.f16.f32 "
        "{%0,%1,%2,%3}, {%4,%5,%6,%7}, {%8,%9}, {%0,%1,%2,%3};"
        : "+f"(d[0]), "+f"(d[1]), "+f"(d[2]), "+f"(d[3])
        : "r"(a[0]), "r"(a[1]), "r"(a[2]), "r"(a[3]), "r"(b[0]), "r"(b[1]));
}

__device__ __forceinline__ void cpasync16(uint32_t dst, const void* src) {
    asm volatile("cp.async.cg.shared.global [%0], [%1], 16;"
                 :: "r"(dst), "l"(src) : "memory");
}

__device__ __forceinline__ void hg_issue(
    uint32_t sb, int p,
    const __half* __restrict__ Ah, const __half* __restrict__ Al,
    const uint32_t* __restrict__ Bh, const uint32_t* __restrict__ Bl,
    int rowBase, int K, int Nc, int colBase, int k0, int t)
{
    uint32_t base = sb + p * HG_BUF;
    // A: thread t owns row t; 4x16B chunks each for hi and lo (64B = 32 halfs = BK)
    {
        const __half* srcH = Ah + (size_t)(rowBase + t) * K + k0;
        const __half* srcL = Al + (size_t)(rowBase + t) * K + k0;
        uint32_t dH = base + t * 80;
        uint32_t dL = base + 10240 + t * 80;
#pragma unroll
        for (int q = 0; q < 4; q++) {
            cpasync16(dH + q * 16, srcH + q * 8);
            cpasync16(dL + q * 16, srcL + q * 8);
        }
    }
    // B: 16 k2-rows x 16 chunks of 16B (4 n-pairs); thread t: row t>>3, chunks (t&7)*2..+1
    {
        int lk2 = t >> 3;
        int k2g = (k0 >> 1) + lk2;
        int q0  = (t & 7) * 2;
        const uint32_t* sh = Bh + (size_t)k2g * Nc + colBase;
        const uint32_t* sl = Bl + (size_t)k2g * Nc + colBase;
        uint32_t dH = base + 20480 + lk2 * 288;
        uint32_t dL = base + 25088 + lk2 * 288;
#pragma unroll
        for (int qq = 0; qq < 2; qq++) {
            int q = q0 + qq;
            cpasync16(dH + q * 16, sh + q * 4);
            cpasync16(dL + q * 16, sl + q * 4);
        }
    }
}

__global__ void __launch_bounds__(128) hgemm_k(
    const __half* __restrict__ Ah, const __half* __restrict__ Al,
    const uint32_t* __restrict__ Bh, const uint32_t* __restrict__ Bl,
    float* __restrict__ C, int M, int K, int Nc)
{
    extern __shared__ char smemc[];
    uint32_t sb = smem_to_u32_helper(smemc);
    int t = threadIdx.x, wid = t >> 5, lane = t & 31;
    int r = lane >> 2, c = lane & 3;
    int wm = (wid >> 1) * 64;     // warp m offset (0 or 64)
    int wn = (wid & 1) * 32;      // warp n offset (0 or 32)
    int rowBase = blockIdx.x * 128;
    int colBase = blockIdx.y * 64;

    float acc[4][4][4] = {};
    int nch = K >> 5;

    hg_issue(sb, 0, Ah, Al, Bh, Bl, rowBase, K, Nc, colBase, 0, t);
    asm volatile("cp.async.commit_group;" ::: "memory");

    for (int i = 0; i < nch; i++) {
        if (i + 1 < nch) {
            hg_issue(sb, (i + 1) & 1, Ah, Al, Bh, Bl, rowBase, K, Nc, colBase,
                     (i + 1) * 32, t);
            asm volatile("cp.async.commit_group;" ::: "memory");
            asm volatile("cp.async.wait_group 1;" ::: "memory");
        } else {
            asm volatile("cp.async.wait_group 0;" ::: "memory");
        }
        __syncthreads();

        const uint32_t* AH = (const uint32_t*)(smemc + (i & 1) * HG_BUF);
        const uint32_t* AL = AH + 2560;   // +10240B
        const uint32_t* BH = AH + 5120;   // +20480B
        const uint32_t* BL = AH + 6272;   // +25088B

#pragma unroll
        for (int kb = 0; kb < 16; kb += 8) {
            uint32_t a[4][4], bh[4][2], bl[4][2];
#pragma unroll
            for (int ni = 0; ni < 4; ni++) {
                int n0 = wn + ni * 8 + r;
                bh[ni][0] = BH[(kb + c) * 72 + n0];
                bh[ni][1] = BH[(kb + c + 4) * 72 + n0];
                bl[ni][0] = BL[(kb + c) * 72 + n0];
                bl[ni][1] = BL[(kb + c + 4) * 72 + n0];
            }
            // pass 1: aH * (bH, bL)
#pragma unroll
            for (int mi = 0; mi < 4; mi++) {
                int m0 = wm + mi * 16 + r;
                a[mi][0] = AH[(m0)     * 20 + kb + c];
                a[mi][1] = AH[(m0 + 8) * 20 + kb + c];
                a[mi][2] = AH[(m0)     * 20 + kb + c + 4];
                a[mi][3] = AH[(m0 + 8) * 20 + kb + c + 4];
            }
#pragma unroll
            for (int mi = 0; mi < 4; mi++)
#pragma unroll
                for (int ni = 0; ni < 4; ni++) {
                    mma_f16(acc[mi][ni], a[mi], bh[ni]);
                    mma_f16(acc[mi][ni], a[mi], bl[ni]);
                }
            // pass 2: aL * bH (reuse a registers)
#pragma unroll
            for (int mi = 0; mi < 4; mi++) {
                int m0 = wm + mi * 16 + r;
                a[mi][0] = AL[(m0)     * 20 + kb + c];
                a[mi][1] = AL[(m0 + 8) * 20 + kb + c];
                a[mi][2] = AL[(m0)     * 20 + kb + c + 4];
                a[mi][3] = AL[(m0 + 8) * 20 + kb + c + 4];
            }
#pragma unroll
            for (int mi = 0; mi < 4; mi++)
#pragma unroll
                for (int ni = 0; ni < 4; ni++)
                    mma_f16(acc[mi][ni], a[mi], bh[ni]);
        }
        __syncthreads();
    }

    // ---- epilogue ----
#pragma unroll
    for (int mi = 0; mi < 4; mi++) {
        int gm0 = rowBase + wm + mi * 16 + r;
#pragma unroll
        for (int ni = 0; ni < 4; ni++) {
            int gn = colBase + wn + ni * 8 + 2 * c;
            if (gm0 < M) {
                C[(size_t)gm0 * Nc + gn]     = acc[mi][ni][0];
                C[(size_t)gm0 * Nc + gn + 1] = acc[mi][ni][1];
            }
            if (gm0 + 8 < M) {
                C[(size_t)(gm0 + 8) * Nc + gn]     = acc[mi][ni][2];
                C[(size_t)(gm0 + 8) * Nc + gn + 1] = acc[mi][ni][3];
            }
        }
    }
}

// ---------------- normalized aggregation (float4) + fp16 hi/lo output -------------
// out[d,:] = act( dinv[d]*( sum_s dinv[s]*h[s,:] + dinv[d]*h[d,:] ) + b )
__global__ __launch_bounds__(256) void agg_k(const float* __restrict__ h,
                                             float* __restrict__ outF,
                                             __half* __restrict__ outH,
                                             __half* __restrict__ outL,
                                             const float* __restrict__ bias,
                                             int F, int relu, int n) {
    int tpn   = F >> 2;                    // threads per node (64/32/16)
    int npb   = 256 / tpn;                 // nodes per block
    int local = threadIdx.x / tpn;
    int fl    = threadIdx.x - local * tpn;
    int d     = blockIdx.x * npb + local;
    if (d >= n) return;

    const float4* hp = (const float4*)h;
    float dv = g_dinv[d];
    float4 acc = hp[(size_t)d * tpn + fl];
    acc.x *= dv; acc.y *= dv; acc.z *= dv; acc.w *= dv;

    int beg = g_rowptr[d], end = g_rowptr[d + 1];
    int j = beg;
    for (; j + 1 < end; j += 2) {
        int s0 = g_col[j], s1 = g_col[j + 1];
        float w0 = g_dinv[s0], w1 = g_dinv[s1];
        float4 v0 = hp[(size_t)s0 * tpn + fl];
        float4 v1 = hp[(size_t)s1 * tpn + fl];
        acc.x += w0 * v0.x + w1 * v1.x;
        acc.y += w0 * v0.y + w1 * v1.y;
        acc.z += w0 * v0.z + w1 * v1.z;
        acc.w += w0 * v0.w + w1 * v1.w;
    }
    if (j < end) {
        int s = g_col[j];
        float w = g_dinv[s];
        float4 v = hp[(size_t)s * tpn + fl];
        acc.x += w * v.x; acc.y += w * v.y; acc.z += w * v.z; acc.w += w * v.w;
    }

    float4 b4 = ((const float4*)bias)[fl];
    float4 o;
    o.x = dv * acc.x + b4.x;
    o.y = dv * acc.y + b4.y;
    o.z = dv * acc.z + b4.z;
    o.w = dv * acc.w + b4.w;
    if (relu) {
        o.x = fmaxf(o.x, 0.f); o.y = fmaxf(o.y, 0.f);
        o.z = fmaxf(o.z, 0.f); o.w = fmaxf(o.w, 0.f);
    }
    if (outF) ((float4*)outF)[(size_t)d * tpn + fl] = o;
    if (outH) {
        __half2 h0 = split_hi2(o.x, o.y);
        __half2 h1 = split_hi2(o.z, o.w);
        __half2 l0 = split_lo2(o.x, o.y, h0);
        __half2 l1 = split_lo2(o.z, o.w, h1);
        ((uint2*)(outH + (size_t)d * F))[fl] = make_uint2(*(uint32_t*)&h0, *(uint32_t*)&h1);
        ((uint2*)(outL + (size_t)d * F))[fl] = make_uint2(*(uint32_t*)&l0, *(uint32_t*)&l1);
    }
}

// ---------------- global mean pool (float4, accumulate) ---------------------------
__global__ void pool_k(const float* __restrict__ h, const void* batch, int n) {
    int t  = threadIdx.x;
    int d  = blockIdx.x * 16 + (t >> 4);
    int fl = t & 15;
    if (d >= n) return;
    int is64 = g_is64;
    int b = load_idx(batch, d, is64);
    float4 v = ((const float4*)h)[(size_t)d * 16 + fl];
    atomicAdd(&g_pool[b * 64 + fl * 4 + 0], v.x);
    atomicAdd(&g_pool[b * 64 + fl * 4 + 1], v.y);
    atomicAdd(&g_pool[b * 64 + fl * 4 + 2], v.z);
    atomicAdd(&g_pool[b * 64 + fl * 4 + 3], v.w);
    if (fl == 0) atomicAdd(&g_cnt[b], 1);
}

// ---------------- final head ------------------------------------------------------
__global__ void final_k(const float* __restrict__ Wl, const float* __restrict__ bl,
                        float* __restrict__ out, int G) {
    int t = threadIdx.x;
    if (t >= G * 2) return;
    int g = t >> 1, c = t & 1;
    float cn = fmaxf((float)g_cnt[g], 1.0f);
    float s = 0.0f;
#pragma unroll
    for (int k = 0; k < 64; k++)
        s += (g_pool[g * 64 + k] / cn) * Wl[k * 2 + c];
    out[t] = s + bl[c];
}

// ---------------- launch ----------------------------------------------------------
extern "C" void kernel_launch(void* const* d_in, const int* in_sizes, int n_in,
                              void* d_out, int out_size) {
    const float* x   = (const float*)d_in[0];
    const void*  ei  = d_in[1];
    const void*  bat = d_in[2];
    const float* W1  = (const float*)d_in[3];
    const float* b1  = (const float*)d_in[4];
    const float* W2  = (const float*)d_in[5];
    const float* b2  = (const float*)d_in[6];
    const float* W3  = (const float*)d_in[7];
    const float* b3  = (const float*)d_in[8];
    const float* Wl  = (const float*)d_in[9];
    const float* bl  = (const float*)d_in[10];
    float* out = (float*)d_out;

    int n = in_sizes[0] / 512;   // 50000
    int E = in_sizes[1] / 2;     // 800000
    int G = out_size / 2;        // 64

    float  *h, *agg;
    __half *ah, *al;
    uint32_t *wh, *wl;
    cudaGetSymbolAddress((void**)&h,   g_h);
    cudaGetSymbolAddress((void**)&agg, g_agg);
    cudaGetSymbolAddress((void**)&ah,  g_ah);
    cudaGetSymbolAddress((void**)&al,  g_al);
    cudaGetSymbolAddress((void**)&wh,  g_wh);
    cudaGetSymbolAddress((void**)&wl,  g_wl);

    static int smem_set = 0;
    if (!smem_set) {
        cudaFuncSetAttribute(hgemm_k, cudaFuncAttributeMaxDynamicSharedMemorySize,
                             HG_SMEM);
        smem_set = 1;
    }

    int gy = (n + 127) / 128;
    const int OFF1 = 0, OFF2 = 65536, OFF3 = 81920;

    // launches 0..4, then hgemm layer1 at index 5 (ncu -s 5 -c 1 capture slot)
    detect_k<<<1, 128>>>(ei);
    convx_k<<<(n * 512 / 2 + 255) / 256, 256>>>(x, n * 512 / 2);
    convw_k<<<(256 * 256 + 255) / 256, 256>>>(W1, 512, 256, OFF1);
    convw_k<<<(128 * 128 + 255) / 256, 256>>>(W2, 256, 128, OFF2);
    convw_k<<<(64 * 64 + 255) / 256, 256>>>(W3, 128, 64, OFF3);
    {
        dim3 grid(gy, 4);   // Nc=256 -> 4 column tiles of 64
        hgemm_k<<<grid, 128, HG_SMEM>>>(ah, al, wh + OFF1, wl + OFF1, h, n, 512, 256);
    }

    // graph structure
    init_k<<<256, 256>>>(n);
    deg_k<<<(E + 255) / 256, 256>>>(ei, E);
    dinv_k<<<(n + 255) / 256, 256>>>(n);
    scan_k<<<1, 1024>>>(n);
    scat_k<<<(E + 255) / 256, 256>>>(ei, E);

    // layer 1 aggregation: F=256 -> fp16 hi/lo for next GEMM
    agg_k<<<(n + 3) / 4, 256>>>(h, nullptr, ah, al, b1, 256, 1, n);

    // layer 2: 256 -> 128
    {
        dim3 grid(gy, 2);
        hgemm_k<<<grid, 128, HG_SMEM>>>(ah, al, wh + OFF2, wl + OFF2, h, n, 256, 128);
        agg_k<<<(n + 7) / 8, 256>>>(h, nullptr, ah, al, b2, 128, 1, n);
    }
    // layer 3: 128 -> 64
    {
        dim3 grid(gy, 1);
        hgemm_k<<<grid, 128, HG_SMEM>>>(ah, al, wh + OFF3, wl + OFF3, h, n, 128, 64);
        agg_k<<<(n + 15) / 16, 256>>>(h, agg, nullptr, nullptr, b3, 64, 0, n);
    }
    // pool + head
    pool_k<<<(n + 15) / 16, 256>>>(agg, bat, n);
    final_k<<<1, 128>>>(Wl, bl, out, G);
}

// round 16
// speedup vs baseline: 1.5663x; 1.5663x over previous
#include <cuda_runtime.h>
#include <cuda_bf16.h>
#include <math.h>
#include <stdint.h>

#define MAXN 50000
#define MAXE 800000
#define MAXG 64

// ---------------- scratch ---------------------------------------------------------
__device__ float g_h[(size_t)MAXN * 256];    // GEMM output (pre-aggregation)
__device__ float g_agg[(size_t)MAXN * 256];  // aggregation output (layer input)
__device__ float g_dinv[MAXN];
__device__ int   g_deg[MAXN];
__device__ int   g_rowptr[MAXN + 1];
__device__ int   g_fill[MAXN];
__device__ int   g_col[MAXE];
__device__ float g_pool[MAXG * 64];
__device__ int   g_cnt[MAXG];
__device__ int   g_is64;

// ---------------- index dtype detection (int64 vs int32) -------------------------
__global__ void detect_k(const void* ei) {
    __shared__ int nz;
    if (threadIdx.x == 0) nz = 0;
    __syncthreads();
    const int* p = (const int*)ei;
    if (p[2 * threadIdx.x + 1] != 0) atomicAdd(&nz, 1);
    __syncthreads();
    if (threadIdx.x == 0) g_is64 = (nz == 0) ? 1 : 0;
}

__device__ __forceinline__ int load_idx(const void* p, long long i, int is64) {
    if (is64) return (int)((const long long*)p)[i];
    return ((const int*)p)[i];
}

// ---------------- init ------------------------------------------------------------
__global__ void init_k(int n) {
    int i = blockIdx.x * blockDim.x + threadIdx.x;
    int stride = gridDim.x * blockDim.x;
    for (; i < n; i += stride) {
        g_deg[i]  = 1;
        g_fill[i] = 0;
        if (i < MAXG * 64) g_pool[i] = 0.0f;
        if (i < MAXG) g_cnt[i] = 0;
    }
}

__global__ void deg_k(const void* ei, int E) {
    int e = blockIdx.x * blockDim.x + threadIdx.x;
    if (e >= E) return;
    int is64 = g_is64;
    int d = load_idx(ei, (long long)E + e, is64);
    atomicAdd(&g_deg[d], 1);
}

__global__ void dinv_k(int n) {
    int i = blockIdx.x * blockDim.x + threadIdx.x;
    if (i < n) g_dinv[i] = rsqrtf((float)g_deg[i]);
}

// ---------------- single-block exclusive scan of (deg-1) -> rowptr ----------------
__global__ void scan_k(int n) {
    __shared__ int part[1024];
    int t = threadIdx.x;
    int C = (n + 1023) / 1024;
    int lo = t * C;
    int hi = min(lo + C, n);
    int s = 0;
    for (int i = lo; i < hi; i++) s += g_deg[i] - 1;
    part[t] = s;
    __syncthreads();
    for (int off = 1; off < 1024; off <<= 1) {
        int v = (t >= off) ? part[t - off] : 0;
        __syncthreads();
        part[t] += v;
        __syncthreads();
    }
    int run = (t == 0) ? 0 : part[t - 1];
    for (int i = lo; i < hi; i++) {
        g_rowptr[i] = run;
        run += g_deg[i] - 1;
    }
    if (t == 1023) g_rowptr[n] = part[1023];
}

__global__ void scat_k(const void* ei, int E) {
    int e = blockIdx.x * blockDim.x + threadIdx.x;
    if (e >= E) return;
    int is64 = g_is64;
    int s = load_idx(ei, e, is64);
    int d = load_idx(ei, (long long)E + e, is64);
    int pos = atomicAdd(&g_fill[d], 1);
    g_col[g_rowptr[d] + pos] = s;
}

// ---------------- 3xBF16 tensor-core GEMM (conflict-free smem) --------------------
// C[MxNc] = A[MxK] @ B[KxNc], row-major. Tile 128x64, BK=32, 8 warps (256 thr).
// bf16 split: a = aH + aL; C += aH*bH + aH*bL + aL*bH.
// Bank-conflict audit:
//   A store: thread = (m=t>>1, h=t&1), addr k2*136 + (m ^ 16h) -> 32 distinct banks.
//   A frag read: xor is constant per unrolled kstep -> perfect 8c+r pattern.
//   B store: consecutive nn within warp -> conflict-free.
//   B frag read: SNB=72 (== 8 mod 32) -> perfect 8c+r pattern.
#define BM 128
#define BN 64
#define BK 32
#define NK2 16      // BK/2 k2-slots
#define SMA 136     // As row stride (u32)
#define SNB 72      // Bs row stride (u32); 72 % 32 == 8 -> conflict-free frag reads

__device__ __forceinline__ void mma_bf16(float* d, const uint32_t* a, const uint32_t* b) {
    asm volatile(
        "mma.sync.aligned.m16n8k16.row.col.f32.bf16.bf16.f32 "
        "{%0,%1,%2,%3}, {%4,%5,%6,%7}, {%8,%9}, {%0,%1,%2,%3};"
        : "+f"(d[0]), "+f"(d[1]), "+f"(d[2]), "+f"(d[3])
        : "r"(a[0]), "r"(a[1]), "r"(a[2]), "r"(a[3]), "r"(b[0]), "r"(b[1]));
}

__device__ __forceinline__ uint32_t pack_hi(float x, float y) {
    __nv_bfloat162 v;
    v.x = __float2bfloat16(x);
    v.y = __float2bfloat16(y);
    return *(uint32_t*)&v;
}
__device__ __forceinline__ uint32_t pack_lo(float x, float y) {
    __nv_bfloat162 v;
    float hx = __bfloat162float(__float2bfloat16(x));
    float hy = __bfloat162float(__float2bfloat16(y));
    v.x = __float2bfloat16(x - hx);
    v.y = __float2bfloat16(y - hy);
    return *(uint32_t*)&v;
}

__global__ __launch_bounds__(256) void tgemm_k(const float* __restrict__ A,
                                               const float* __restrict__ B,
                                               float* __restrict__ C,
                                               int M, int K, int Nc) {
    __shared__ uint32_t AsH[NK2 * SMA];
    __shared__ uint32_t AsL[NK2 * SMA];
    __shared__ uint32_t BsH[NK2 * SNB];
    __shared__ uint32_t BsL[NK2 * SNB];

    int t = threadIdx.x, wid = t >> 5, lane = t & 31;
    int wm = (wid >> 1) * 32;       // warp m offset (0,32,64,96)
    int wn = (wid & 1) * 32;        // warp n offset (0,32)
    int r = lane >> 2, c = lane & 3;
    int rowBase = blockIdx.y * BM;
    int colBase = blockIdx.x * BN;

    // A loader geometry: thread owns half-row (m = t>>1, h = t&1 selects 16-float half)
    int hA_ = t & 1, mA_ = t >> 1;
    int rowA = rowBase + mA_;
    int mh   = mA_ ^ (hA_ << 4);    // xor-swizzled m used for all A stores

    float acc[2][4][4] = {};

    float4 a4[4];                   // staged A: 16 floats = 8 k-pairs of this half-row
    float  bReg[8];                 // staged B: e = t + i*256 ; k2 = e>>6, n = e&63

    // ---- prefetch first tile ----
    {
        if (rowA < M) {
            const float4* ap = (const float4*)(A + (size_t)rowA * K + 16 * hA_);
#pragma unroll
            for (int q = 0; q < 4; q++) a4[q] = ap[q];
        } else {
#pragma unroll
            for (int q = 0; q < 4; q++) a4[q] = make_float4(0.f, 0.f, 0.f, 0.f);
        }
#pragma unroll
        for (int i = 0; i < 4; i++) {
            int e = t + i * 256;
            int k2 = e >> 6, nn = e & 63;
            bReg[2 * i]     = B[(size_t)(2 * k2)     * Nc + colBase + nn];
            bReg[2 * i + 1] = B[(size_t)(2 * k2 + 1) * Nc + colBase + nn];
        }
    }

    for (int k0 = 0; k0 < K; k0 += BK) {
        // ---- store staged A tile (convert to bf16 hi/lo, xor-swizzled, conflict-free)
#pragma unroll
        for (int q = 0; q < 4; q++) {
            int k2a = 8 * hA_ + 2 * q;
            AsH[(k2a)     * SMA + mh] = pack_hi(a4[q].x, a4[q].y);
            AsL[(k2a)     * SMA + mh] = pack_lo(a4[q].x, a4[q].y);
            AsH[(k2a + 1) * SMA + mh] = pack_hi(a4[q].z, a4[q].w);
            AsL[(k2a + 1) * SMA + mh] = pack_lo(a4[q].z, a4[q].w);
        }
        // ---- store staged B tile ----
#pragma unroll
        for (int i = 0; i < 4; i++) {
            int e = t + i * 256;
            int k2 = e >> 6, nn = e & 63;
            BsH[k2 * SNB + nn] = pack_hi(bReg[2 * i], bReg[2 * i + 1]);
            BsL[k2 * SNB + nn] = pack_lo(bReg[2 * i], bReg[2 * i + 1]);
        }
        __syncthreads();

        // ---- prefetch next tile (global latency hidden behind MMAs) ----
        if (k0 + BK < K) {
            int kn = k0 + BK;
            if (rowA < M) {
                const float4* ap = (const float4*)(A + (size_t)rowA * K + kn + 16 * hA_);
#pragma unroll
                for (int q = 0; q < 4; q++) a4[q] = ap[q];
            }
#pragma unroll
            for (int i = 0; i < 4; i++) {
                int e = t + i * 256;
                int k2 = e >> 6, nn = e & 63;
                bReg[2 * i]     = B[(size_t)(kn + 2 * k2)     * Nc + colBase + nn];
                bReg[2 * i + 1] = B[(size_t)(kn + 2 * k2 + 1) * Nc + colBase + nn];
            }
        }

        // ---- MMA: 2 ksteps of k16 ----
#pragma unroll
        for (int ks = 0; ks < 2; ks++) {
            int kb = ks * 8;  // k2 base
            // xor constants: (kb+c)>>3 is constant over c=0..3 after unroll
            int x0 = ((kb >> 3) & 1) << 4;        // for k2 index kb+c
            int x4 = (((kb + 4) >> 3) & 1) << 4;  // for k2 index kb+c+4
            uint32_t aH[2][4], aL[2][4], bH[4][2], bL[4][2];
#pragma unroll
            for (int mi = 0; mi < 2; mi++) {
                int m0 = wm + mi * 16 + r;
                aH[mi][0] = AsH[(kb + c)     * SMA + ((m0)     ^ x0)];
                aH[mi][1] = AsH[(kb + c)     * SMA + ((m0 + 8) ^ x0)];
                aH[mi][2] = AsH[(kb + c + 4) * SMA + ((m0)     ^ x4)];
                aH[mi][3] = AsH[(kb + c + 4) * SMA + ((m0 + 8) ^ x4)];
                aL[mi][0] = AsL[(kb + c)     * SMA + ((m0)     ^ x0)];
                aL[mi][1] = AsL[(kb + c)     * SMA + ((m0 + 8) ^ x0)];
                aL[mi][2] = AsL[(kb + c + 4) * SMA + ((m0)     ^ x4)];
                aL[mi][3] = AsL[(kb + c + 4) * SMA + ((m0 + 8) ^ x4)];
            }
#pragma unroll
            for (int ni = 0; ni < 4; ni++) {
                int n0 = wn + ni * 8 + r;
                bH[ni][0] = BsH[(kb + c)     * SNB + n0];
                bH[ni][1] = BsH[(kb + c + 4) * SNB + n0];
                bL[ni][0] = BsL[(kb + c)     * SNB + n0];
                bL[ni][1] = BsL[(kb + c + 4) * SNB + n0];
            }
#pragma unroll
            for (int mi = 0; mi < 2; mi++)
#pragma unroll
                for (int ni = 0; ni < 4; ni++) {
                    mma_bf16(acc[mi][ni], aL[mi], bH[ni]);
                    mma_bf16(acc[mi][ni], aH[mi], bL[ni]);
                    mma_bf16(acc[mi][ni], aH[mi], bH[ni]);
                }
        }
        __syncthreads();
    }

    // ---- store C ----
#pragma unroll
    for (int mi = 0; mi < 2; mi++) {
        int gm0 = rowBase + wm + mi * 16 + r;
#pragma unroll
        for (int ni = 0; ni < 4; ni++) {
            int gn = colBase + wn + ni * 8 + 2 * c;
            if (gm0 < M) {
                C[(size_t)gm0 * Nc + gn]     = acc[mi][ni][0];
                C[(size_t)gm0 * Nc + gn + 1] = acc[mi][ni][1];
            }
            if (gm0 + 8 < M) {
                C[(size_t)(gm0 + 8) * Nc + gn]     = acc[mi][ni][2];
                C[(size_t)(gm0 + 8) * Nc + gn + 1] = acc[mi][ni][3];
            }
        }
    }
}

// ---------------- normalized aggregation (float4-vectorized) ----------------------
__global__ __launch_bounds__(256) void agg_k(const float* __restrict__ h,
                                             float* __restrict__ out,
                                             const float* __restrict__ bias,
                                             int F, int relu, int n) {
    int tpn   = F >> 2;                    // threads per node (64/32/16)
    int npb   = 256 / tpn;                 // nodes per block
    int local = threadIdx.x / tpn;
    int fl    = threadIdx.x - local * tpn;
    int d     = blockIdx.x * npb + local;
    if (d >= n) return;

    const float4* hp = (const float4*)h;
    float dv = g_dinv[d];
    float4 acc = hp[(size_t)d * tpn + fl];
    acc.x *= dv; acc.y *= dv; acc.z *= dv; acc.w *= dv;

    int beg = g_rowptr[d], end = g_rowptr[d + 1];
    int j = beg;
    for (; j + 1 < end; j += 2) {
        int s0 = g_col[j], s1 = g_col[j + 1];
        float w0 = g_dinv[s0], w1 = g_dinv[s1];
        float4 v0 = hp[(size_t)s0 * tpn + fl];
        float4 v1 = hp[(size_t)s1 * tpn + fl];
        acc.x += w0 * v0.x + w1 * v1.x;
        acc.y += w0 * v0.y + w1 * v1.y;
        acc.z += w0 * v0.z + w1 * v1.z;
        acc.w += w0 * v0.w + w1 * v1.w;
    }
    if (j < end) {
        int s = g_col[j];
        float w = g_dinv[s];
        float4 v = hp[(size_t)s * tpn + fl];
        acc.x += w * v.x; acc.y += w * v.y; acc.z += w * v.z; acc.w += w * v.w;
    }

    float4 b4 = ((const float4*)bias)[fl];
    float4 o;
    o.x = dv * acc.x + b4.x;
    o.y = dv * acc.y + b4.y;
    o.z = dv * acc.z + b4.z;
    o.w = dv * acc.w + b4.w;
    if (relu) {
        o.x = fmaxf(o.x, 0.f); o.y = fmaxf(o.y, 0.f);
        o.z = fmaxf(o.z, 0.f); o.w = fmaxf(o.w, 0.f);
    }
    ((float4*)out)[(size_t)d * tpn + fl] = o;
}

// ---------------- global mean pool (float4, accumulate) ---------------------------
__global__ void pool_k(const float* __restrict__ h, const void* batch, int n) {
    int t  = threadIdx.x;
    int d  = blockIdx.x * 16 + (t >> 4);
    int fl = t & 15;
    if (d >= n) return;
    int is64 = g_is64;
    int b = load_idx(batch, d, is64);
    float4 v = ((const float4*)h)[(size_t)d * 16 + fl];
    atomicAdd(&g_pool[b * 64 + fl * 4 + 0], v.x);
    atomicAdd(&g_pool[b * 64 + fl * 4 + 1], v.y);
    atomicAdd(&g_pool[b * 64 + fl * 4 + 2], v.z);
    atomicAdd(&g_pool[b * 64 + fl * 4 + 3], v.w);
    if (fl == 0) atomicAdd(&g_cnt[b], 1);
}

// ---------------- final head ------------------------------------------------------
__global__ void final_k(const float* __restrict__ Wl, const float* __restrict__ bl,
                        float* __restrict__ out, int G) {
    int t = threadIdx.x;
    if (t >= G * 2) return;
    int g = t >> 1, c = t & 1;
    float cn = fmaxf((float)g_cnt[g], 1.0f);
    float s = 0.0f;
#pragma unroll
    for (int k = 0; k < 64; k++)
        s += (g_pool[g * 64 + k] / cn) * Wl[k * 2 + c];
    out[t] = s + bl[c];
}

// ---------------- launch ----------------------------------------------------------
extern "C" void kernel_launch(void* const* d_in, const int* in_sizes, int n_in,
                              void* d_out, int out_size) {
    const float* x   = (const float*)d_in[0];
    const void*  ei  = d_in[1];
    const void*  bat = d_in[2];
    const float* W1  = (const float*)d_in[3];
    const float* b1  = (const float*)d_in[4];
    const float* W2  = (const float*)d_in[5];
    const float* b2  = (const float*)d_in[6];
    const float* W3  = (const float*)d_in[7];
    const float* b3  = (const float*)d_in[8];
    const float* Wl  = (const float*)d_in[9];
    const float* bl  = (const float*)d_in[10];
    float* out = (float*)d_out;

    int n = in_sizes[0] / 512;   // 50000
    int E = in_sizes[1] / 2;     // 800000
    int G = out_size / 2;        // 64

    float *h, *agg;
    cudaGetSymbolAddress((void**)&h, g_h);
    cudaGetSymbolAddress((void**)&agg, g_agg);

    int gy = (n + BM - 1) / BM;

    // graph build interleaved with layer-1 GEMM (same launch order as the round
    // that captured tgemm_k in the ncu slot)
    detect_k<<<1, 128>>>(ei);
    init_k<<<256, 256>>>(n);
    deg_k<<<(E + 255) / 256, 256>>>(ei, E);
    {
        dim3 grid(256 / BN, gy);
        tgemm_k<<<grid, 256>>>(x, W1, h, n, 512, 256);
    }
    dinv_k<<<(n + 255) / 256, 256>>>(n);
    scan_k<<<1, 1024>>>(n);
    scat_k<<<(E + 255) / 256, 256>>>(ei, E);

    // --- layer 1 aggregation: F=256, 4 nodes/block ---
    agg_k<<<(n + 3) / 4, 256>>>(h, agg, b1, 256, 1, n);

    // --- layer 2: 256 -> 128 ---
    {
        dim3 grid(128 / BN, gy);
        tgemm_k<<<grid, 256>>>(agg, W2, h, n, 256, 128);
        agg_k<<<(n + 7) / 8, 256>>>(h, agg, b2, 128, 1, n);
    }
    // --- layer 3: 128 -> 64 ---
    {
        dim3 grid(64 / BN, gy);
        tgemm_k<<<grid, 256>>>(agg, W3, h, n, 128, 64);
        agg_k<<<(n + 15) / 16, 256>>>(h, agg, b3, 64, 0, n);
    }
    // --- pool + head ---
    pool_k<<<(n + 15) / 16, 256>>>(agg, bat, n);
    final_k<<<1, 128>>>(Wl, bl, out, G);
}